// round 10
// baseline (speedup 1.0000x reference)
#include <cuda_runtime.h>
#include <math.h>
#include <stdint.h>

#define MAX_ROWS    32768
#define HSZ         32768                 // hash table slots (power of 2)
#define MAX_PBLK    64                    // probe-kernel blocks

// ---------------- device scratch (no allocations allowed) ----------------
// Fully overwritten each launch in dependency order:
//   row kernel:  g_rowsum, g_jfirst, g_next + g_head (reset then insert),
//                resets g_done
//   probe kernel: g_msum, g_mcnt, increments g_done
__device__ float g_rowsum[MAX_ROWS];
__device__ int   g_jfirst[MAX_ROWS];
__device__ int   g_head[HSZ];
__device__ int   g_next[MAX_ROWS];
__device__ float g_msum[MAX_PBLK];
__device__ int   g_mcnt[MAX_PBLK];
__device__ int   g_done;

__device__ __forceinline__ uint32_t hash_x(float x) {
    uint32_t u = __float_as_uint(x) * 2654435761u;
    return (u >> 17) & (HSZ - 1);         // top 15 bits
}

// ---------------- kernel 1: one block (128 thr) per row of [B*L, L] -------
// PROVEN 45.0us stream (R2/R3/R9): gt via __ldcs, cm gathered only where
// gt != 0, first j with gt>0. Epilogue now also inserts this row into the
// x-keyed hash (valid rows only). Heads are reset by blocks 0..HSZ/128-1 as
// their FIRST instructions (all wave-1); earliest insert trails a full
// DRAM-bound row scan, so reset always completes first.
__global__ void __launch_bounds__(128) mc_row_kernel(
    const float* __restrict__ cm,
    const float* __restrict__ gt,
    const float* __restrict__ samples0,
    int L)
{
    // interleaved hash-head reset + done-counter reset
    for (int i = blockIdx.x * 128 + threadIdx.x; i < HSZ; i += gridDim.x * 128)
        g_head[i] = -1;
    if (blockIdx.x == 0 && threadIdx.x == 0) g_done = 0;

    const int row = blockIdx.x;
    const long long base = (long long)row * (long long)L;
    const float*  gr = gt + base;
    const float*  cr = cm + base;
    const float4* g4 = (const float4*)gr;
    const int nv = L >> 2;

    float lsum = 0.0f;
    int   lmin = 0x7fffffff;

    // chunks of 1024 float4s: 8 streaming loads/thread, front-batched (MLP=8)
    int v0 = 0;
    for (; v0 + 1024 <= nv; v0 += 1024) {
        float4 r[8];
        #pragma unroll
        for (int i = 0; i < 8; i++)
            r[i] = __ldcs(&g4[v0 + threadIdx.x + i * 128]);
        #pragma unroll
        for (int i = 0; i < 8; i++) {
            const float4 g = r[i];
            if (g.x != 0.0f || g.y != 0.0f || g.z != 0.0f || g.w != 0.0f) {
                const int j = (v0 + threadIdx.x + i * 128) << 2;
                if (g.x != 0.0f) lsum += g.x * __logf(cr[j + 0] + 1e-6f);
                if (g.y != 0.0f) lsum += g.y * __logf(cr[j + 1] + 1e-6f);
                if (g.z != 0.0f) lsum += g.z * __logf(cr[j + 2] + 1e-6f);
                if (g.w != 0.0f) lsum += g.w * __logf(cr[j + 3] + 1e-6f);
                if      (g.x > 0.0f) lmin = min(lmin, j + 0);
                else if (g.y > 0.0f) lmin = min(lmin, j + 1);
                else if (g.z > 0.0f) lmin = min(lmin, j + 2);
                else if (g.w > 0.0f) lmin = min(lmin, j + 3);
            }
        }
    }
    // remainder float4s
    for (int v = v0 + threadIdx.x; v < nv; v += 128) {
        const float4 g = __ldcs(&g4[v]);
        if (g.x != 0.0f || g.y != 0.0f || g.z != 0.0f || g.w != 0.0f) {
            const int j = v << 2;
            if (g.x != 0.0f) lsum += g.x * __logf(cr[j + 0] + 1e-6f);
            if (g.y != 0.0f) lsum += g.y * __logf(cr[j + 1] + 1e-6f);
            if (g.z != 0.0f) lsum += g.z * __logf(cr[j + 2] + 1e-6f);
            if (g.w != 0.0f) lsum += g.w * __logf(cr[j + 3] + 1e-6f);
            if      (g.x > 0.0f) lmin = min(lmin, j + 0);
            else if (g.y > 0.0f) lmin = min(lmin, j + 1);
            else if (g.z > 0.0f) lmin = min(lmin, j + 2);
            else if (g.w > 0.0f) lmin = min(lmin, j + 3);
        }
    }
    // scalar tail
    for (int j = (nv << 2) + threadIdx.x; j < L; j += 128) {
        const float g = gr[j];
        if (g != 0.0f) lsum += g * __logf(cr[j] + 1e-6f);
        if (g > 0.0f)  lmin = min(lmin, j);
    }

    // block reduce (4 warps)
    #pragma unroll
    for (int o = 16; o > 0; o >>= 1) {
        lsum += __shfl_down_sync(0xffffffffu, lsum, o);
        lmin  = min(lmin, __shfl_down_sync(0xffffffffu, lmin, o));
    }
    __shared__ float ws[4];
    __shared__ int   wm[4];
    const int wid = threadIdx.x >> 5;
    if ((threadIdx.x & 31) == 0) { ws[wid] = lsum; wm[wid] = lmin; }
    __syncthreads();
    if (threadIdx.x == 0) {
        lsum = ws[0] + ws[1] + ws[2] + ws[3];
        lmin = min(min(wm[0], wm[1]), min(wm[2], wm[3]));
        g_rowsum[row] = lsum;
        const bool valid = (lmin < 0x7fffffff);
        g_jfirst[row] = valid ? lmin : -1;
        if (valid) {
            // hash insert for this row (heads already reset; see note above)
            const float x = ((const float2*)samples0)[row].x;
            g_next[row] = atomicExch(&g_head[hash_x(x)], row);
        }
    }
}

// ---------------- kernel 2: probe + last-block finalize --------------------
__global__ void __launch_bounds__(256) mc_probefin_kernel(
    const float* __restrict__ samples0,
    const float* __restrict__ samples1,
    const float* __restrict__ mkpts0,
    const float* __restrict__ mkpts1,
    float* __restrict__ out,
    int L, int N, int rows, int pb, float Bf)
{
    const int tid = threadIdx.x;
    const int n = blockIdx.x * 256 + tid;

    float fs = 0.0f;
    int   fc = 0;
    if (n < N) {
        const float bf = mkpts0[3 * n + 0];
        const float x  = mkpts0[3 * n + 1];
        const float y  = mkpts0[3 * n + 2];
        const float2* s0 = (const float2*)samples0;

        int best = 0x7fffffff;
        for (int r = g_head[hash_x(x)]; r >= 0; r = g_next[r]) {
            const float2 p = s0[r];
            if (p.x == x && p.y == y && (float)(r / L) == bf)
                best = min(best, r);
        }
        if (best != 0x7fffffff) {
            const int jf = g_jfirst[best];
            const int b  = best / L;
            const float2 q = ((const float2*)samples1)[(long long)b * L + jf];
            const float dx = q.x - mkpts1[2 * n + 0];
            const float dy = q.y - mkpts1[2 * n + 1];
            const float nrm = sqrtf(dx * dx + dy * dy);
            if (nrm < 10.0f) { fs = nrm; fc = 1; }
        }
    }

    #pragma unroll
    for (int o = 16; o > 0; o >>= 1) {
        fs += __shfl_down_sync(0xffffffffu, fs, o);
        fc += __shfl_down_sync(0xffffffffu, fc, o);
    }
    __shared__ float wfs[8];
    __shared__ int   wfc[8];
    const int wid = tid >> 5;
    if ((tid & 31) == 0) { wfs[wid] = fs; wfc[wid] = fc; }
    __syncthreads();

    __shared__ int amLast;
    if (tid == 0) {
        fs = 0.0f; fc = 0;
        #pragma unroll
        for (int i = 0; i < 8; i++) { fs += wfs[i]; fc += wfc[i]; }
        g_msum[blockIdx.x] = fs;
        g_mcnt[blockIdx.x] = fc;
        __threadfence();
        amLast = (atomicAdd(&g_done, 1) == pb - 1);
    }
    __syncthreads();

    if (amLast) {
        // coarse sum + validity directly from per-row arrays (L2-hot, 128KB)
        float cs = 0.0f; fs = 0.0f;
        int   va = 0;    fc = 0;
        for (int i = tid; i < rows; i += 256) {
            cs += g_rowsum[i];
            va |= (g_jfirst[i] >= 0);
        }
        for (int i = tid; i < pb; i += 256) { fs += g_msum[i]; fc += g_mcnt[i]; }
        #pragma unroll
        for (int o = 16; o > 0; o >>= 1) {
            cs += __shfl_down_sync(0xffffffffu, cs, o);
            fs += __shfl_down_sync(0xffffffffu, fs, o);
            fc += __shfl_down_sync(0xffffffffu, fc, o);
            va |= __shfl_down_sync(0xffffffffu, va, o);
        }
        __shared__ float wcs2[8], wfs2[8];
        __shared__ int   wfc2[8], wva2[8];
        if ((tid & 31) == 0) { wcs2[wid] = cs; wfs2[wid] = fs; wfc2[wid] = fc; wva2[wid] = va; }
        __syncthreads();
        if (tid == 0) {
            cs = 0.0f; fs = 0.0f; fc = 0; va = 0;
            #pragma unroll
            for (int i = 0; i < 8; i++) {
                cs += wcs2[i]; fs += wfs2[i]; fc += wfc2[i]; va |= wva2[i];
            }
            const float coarse = -cs / Bf;
            float fine;
            if (va) fine = (fc > 0) ? (fs / (float)fc) : 10.0f;
            else    fine = 1e-6f;
            out[0] = coarse + 1000.0f * fine;
            out[1] = coarse;
            out[2] = fine;
        }
    }
}

extern "C" void kernel_launch(void* const* d_in, const int* in_sizes, int n_in,
                              void* d_out, int out_size)
{
    const float* cm       = (const float*)d_in[0];  // [B,L,L]
    const float* gt       = (const float*)d_in[1];  // [B,L,L]
    const float* samples0 = (const float*)d_in[2];  // [B,L,2]
    const float* samples1 = (const float*)d_in[3];  // [B,L,2]
    const float* mkpts0   = (const float*)d_in[4];  // [N,3]
    const float* mkpts1   = (const float*)d_in[5];  // [N,2]
    float* out = (float*)d_out;

    const long long BL = (long long)in_sizes[2] / 2;       // B*L
    const int L = (int)((long long)in_sizes[0] / BL);      // B*L*L / (B*L)
    const int B = (int)(BL / L);
    const int N = in_sizes[4] / 3;
    const int rows = B * L;
    const int pb = (N + 255) / 256;      // probe blocks

    mc_row_kernel<<<rows, 128>>>(cm, gt, samples0, L);
    mc_probefin_kernel<<<pb, 256>>>(samples0, samples1, mkpts0, mkpts1,
                                    out, L, N, rows, pb, (float)B);
}